// round 17
// baseline (speedup 1.0000x reference)
#include <cuda_runtime.h>
#include <cuda_bf16.h>
#include <math.h>
#include <stdint.h>

#define BB 4
#define SS 2048
#define EE 1024
#define HH 16
#define DD 64
#define MM (BB*SS)

typedef unsigned long long u64;

// Projected v fp32: [B*S, E] row-major (col = h*64 + d)
__device__ float g_v[MM * EE];

// bf16 split planes of inputs (for proj GEMMs)
__device__ uint16_t g_sa[3][3][MM * EE];
__device__ uint16_t g_sw[3][3][EE * EE];
// bf16 split planes of projected q/k (written directly by proj epilogue)
__device__ uint16_t g_qp[3][MM * EE];
__device__ uint16_t g_kp[3][MM * EE];

// ===========================================================================
// helpers
// ===========================================================================
__device__ __forceinline__ uint32_t smem_u32(const void* p) {
    uint32_t a;
    asm("{ .reg .u64 t; cvta.to.shared.u64 t, %1; cvt.u32.u64 %0, t; }"
        : "=r"(a) : "l"(p));
    return a;
}
__device__ __forceinline__ uint32_t sw128(uint32_t off) {
    return off ^ ((off >> 3) & 0x70);
}
__device__ __forceinline__ void split3(float x, uint16_t& b0, uint16_t& b1, uint16_t& b2) {
    __nv_bfloat16 h0 = __float2bfloat16_rn(x);
    float r = x - __bfloat162float(h0);
    __nv_bfloat16 h1 = __float2bfloat16_rn(r);
    r -= __bfloat162float(h1);
    __nv_bfloat16 h2 = __float2bfloat16_rn(r);
    b0 = __bfloat16_as_ushort(h0);
    b1 = __bfloat16_as_ushort(h1);
    b2 = __bfloat16_as_ushort(h2);
}
__device__ __forceinline__ void ldsm4(uint32_t* r, uint32_t addr) {
    asm volatile("ldmatrix.sync.aligned.m8n8.x4.shared.b16 {%0,%1,%2,%3}, [%4];"
        : "=r"(r[0]), "=r"(r[1]), "=r"(r[2]), "=r"(r[3]) : "r"(addr));
}
__device__ __forceinline__ void mma16816(float* c, const uint32_t* a,
                                         uint32_t b0, uint32_t b1) {
    asm volatile("mma.sync.aligned.m16n8k16.row.col.f32.bf16.bf16.f32 "
        "{%0,%1,%2,%3}, {%4,%5,%6,%7}, {%8,%9}, {%0,%1,%2,%3};"
        : "+f"(c[0]), "+f"(c[1]), "+f"(c[2]), "+f"(c[3])
        : "r"(a[0]), "r"(a[1]), "r"(a[2]), "r"(a[3]), "r"(b0), "r"(b1));
}
__device__ __forceinline__ void mma16816_z(float* d, const uint32_t* a,
                                           uint32_t b0, uint32_t b1) {
    asm volatile("mma.sync.aligned.m16n8k16.row.col.f32.bf16.bf16.f32 "
        "{%0,%1,%2,%3}, {%4,%5,%6,%7}, {%8,%9}, {%10,%11,%12,%13};"
        : "=f"(d[0]), "=f"(d[1]), "=f"(d[2]), "=f"(d[3])
        : "r"(a[0]), "r"(a[1]), "r"(a[2]), "r"(a[3]), "r"(b0), "r"(b1),
          "f"(0.0f), "f"(0.0f), "f"(0.0f), "f"(0.0f));
}
// packed f32x2
__device__ __forceinline__ void fma2(u64& c, u64 a, u64 b) {
    asm("fma.rn.f32x2 %0, %1, %2, %0;" : "+l"(c) : "l"(a), "l"(b));
}
__device__ __forceinline__ u64 dup2(float x) {
    u64 o;
    asm("mov.b64 %0, {%1, %1};" : "=l"(o) : "f"(x));
    return o;
}
__device__ __forceinline__ void unpack2(float& l, float& h, u64 u) {
    asm("mov.b64 {%0, %1}, %2;" : "=f"(l), "=f"(h) : "l"(u));
}
#define CPASYNC16(s, g) \
    asm volatile("cp.async.cg.shared.global [%0], [%1], 16;" :: "r"(s), "l"(g))
#define CP_COMMIT() asm volatile("cp.async.commit_group;" ::: "memory")
#define CP_WAIT1()  asm volatile("cp.async.wait_group 1;" ::: "memory")
#define CP_WAIT0()  asm volatile("cp.async.wait_group 0;" ::: "memory")

// ===========================================================================
// Split conversion kernels (inputs only)
// ===========================================================================
__global__ __launch_bounds__(256)
void split_act(const float* __restrict__ q, const float* __restrict__ k,
               const float* __restrict__ v)
{
    const int z = blockIdx.y;
    const float* src = (z == 0) ? q : (z == 1) ? k : v;
    const size_t i = ((size_t)blockIdx.x * 256 + threadIdx.x) * 4;
    const float4 x = *(const float4*)(src + i);
    uint16_t b0[4], b1[4], b2[4];
    split3(x.x, b0[0], b1[0], b2[0]);
    split3(x.y, b0[1], b1[1], b2[1]);
    split3(x.z, b0[2], b1[2], b2[2]);
    split3(x.w, b0[3], b1[3], b2[3]);
    *(ushort4*)&g_sa[z][0][i] = make_ushort4(b0[0], b0[1], b0[2], b0[3]);
    *(ushort4*)&g_sa[z][1][i] = make_ushort4(b1[0], b1[1], b1[2], b1[3]);
    *(ushort4*)&g_sa[z][2][i] = make_ushort4(b2[0], b2[1], b2[2], b2[3]);
}

__global__ __launch_bounds__(256)
void split_w(const float* __restrict__ wq, const float* __restrict__ wk,
             const float* __restrict__ wv)
{
    const int z = blockIdx.y;
    const float* src = (z == 0) ? wq : (z == 1) ? wk : wv;
    const size_t i = ((size_t)blockIdx.x * 256 + threadIdx.x) * 4;
    const float4 x = *(const float4*)(src + i);
    uint16_t b0[4], b1[4], b2[4];
    split3(x.x, b0[0], b1[0], b2[0]);
    split3(x.y, b0[1], b1[1], b2[1]);
    split3(x.z, b0[2], b1[2], b2[2]);
    split3(x.w, b0[3], b1[3], b2[3]);
    *(ushort4*)&g_sw[z][0][i] = make_ushort4(b0[0], b0[1], b0[2], b0[3]);
    *(ushort4*)&g_sw[z][1][i] = make_ushort4(b1[0], b1[1], b1[2], b1[3]);
    *(ushort4*)&g_sw[z][2][i] = make_ushort4(b2[0], b2[1], b2[2], b2[3]);
}

// ===========================================================================
// Projection GEMM via mma.sync, bf16-split (R11 recipe — VALIDATED).
// z=0/1 (Q/K): epilogue splits the fp32 result into 3 bf16 planes and writes
// g_qp/g_kp directly (bitwise-identical to the old split_qk kernel's output).
// z=2 (V): fp32 output to g_v, 2 correction chains.
// ===========================================================================
#define TILE_B   16384
#define STAGE_B  (6 * TILE_B)
#define PROJ_SMEM (2 * STAGE_B)
#define KT_STEPS 16

__global__ __launch_bounds__(256, 1)
void proj_mma(const float* __restrict__ bq, const float* __restrict__ bk,
              const float* __restrict__ bv, float* __restrict__ Cv)
{
    extern __shared__ char smem[];
    const uint32_t sb = smem_u32(smem);
    const int tid = threadIdx.x;
    const int wid = tid >> 5;
    const int l   = tid & 31;
    const int wm = wid >> 2;
    const int wn = wid & 3;

    const int z  = blockIdx.z;
    const int bn = blockIdx.x * 128;
    const int bm = blockIdx.y * 128;
    const float* bias = (z == 0) ? bq : (z == 1) ? bk : bv;
    const int ncorr = (z == 2) ? 2 : 5;

    uint32_t swA[4], swB[2];
#pragma unroll
    for (int mi = 0; mi < 4; mi++)
        swA[mi] = sw128((uint32_t)((wm * 64 + mi * 16 + (l & 15)) * 128
                                   + ((l >> 4) << 4)));
#pragma unroll
    for (int nh = 0; nh < 2; nh++)
        swB[nh] = sw128((uint32_t)((wn * 32 + nh * 16 + ((l >> 4) & 1) * 8
                                    + (l & 7)) * 128 + (((l >> 3) & 1) << 4)));

    float accH[4][4][4];
    float accL[4][4][4];
#pragma unroll
    for (int mi = 0; mi < 4; mi++)
#pragma unroll
        for (int ni = 0; ni < 4; ni++)
#pragma unroll
            for (int c = 0; c < 4; c++) {
                accH[mi][ni][c] = 0.0f;
                accL[mi][ni][c] = 0.0f;
            }

    auto load_stage = [&](int kt, int st) {
        const uint32_t stage = sb + st * STAGE_B;
#pragma unroll
        for (int i = 0; i < 24; i++) {
            const int idx = tid + i * 256;
            const int plane = idx >> 10;
            const int chunk = idx & 1023;
            const int r = chunk >> 3;
            const int c = chunk & 7;
            const uint16_t* gp = (plane < 3)
                ? &g_sa[z][plane][(size_t)(bm + r) * EE + kt * 64 + c * 8]
                : &g_sw[z][plane - 3][(size_t)(bn + r) * EE + kt * 64 + c * 8];
            const uint32_t s = stage + plane * TILE_B + sw128((uint32_t)(r * 128 + c * 16));
            CPASYNC16(s, gp);
        }
        CP_COMMIT();
    };

    load_stage(0, 0);

    const int pa[5] = {1, 0, 2, 1, 0};
    const int pb[5] = {0, 1, 0, 1, 2};

    for (int kt = 0; kt < KT_STEPS; kt++) {
        if (kt + 1 < KT_STEPS) {
            load_stage(kt + 1, (kt + 1) & 1);
            CP_WAIT1();
        } else {
            CP_WAIT0();
        }
        __syncthreads();

        const uint32_t As = sb + (kt & 1) * STAGE_B;
        const uint32_t Bs = As + 3 * TILE_B;

        // ---- main chain (0,0): C=0 HMMA + fp32 RN drain ----
#pragma unroll
        for (int ks = 0; ks < 4; ks++) {
            const uint32_t kx = (uint32_t)(ks << 5);
            uint32_t a[4][4], b[2][4];
#pragma unroll
            for (int mi = 0; mi < 4; mi++)
                ldsm4(a[mi], As + (swA[mi] ^ kx));
#pragma unroll
            for (int nh = 0; nh < 2; nh++)
                ldsm4(b[nh], Bs + (swB[nh] ^ kx));
#pragma unroll
            for (int mi = 0; mi < 4; mi++) {
#pragma unroll
                for (int ni = 0; ni < 4; ni++) {
                    float t[4];
                    const uint32_t bb0 = b[ni >> 1][(ni & 1) * 2];
                    const uint32_t bb1 = b[ni >> 1][(ni & 1) * 2 + 1];
                    mma16816_z(t, a[mi], bb0, bb1);
                    accH[mi][ni][0] += t[0];
                    accH[mi][ni][1] += t[1];
                    accH[mi][ni][2] += t[2];
                    accH[mi][ni][3] += t[3];
                }
            }
        }

        // ---- correction chains -> accL (chained) ----
        for (int p = 0; p < ncorr; p++) {
            const uint32_t at = As + pa[p] * TILE_B;
            const uint32_t bt = Bs + pb[p] * TILE_B;
#pragma unroll
            for (int ks = 0; ks < 4; ks++) {
                const uint32_t kx = (uint32_t)(ks << 5);
                uint32_t a[4][4], b[2][4];
#pragma unroll
                for (int mi = 0; mi < 4; mi++)
                    ldsm4(a[mi], at + (swA[mi] ^ kx));
#pragma unroll
                for (int nh = 0; nh < 2; nh++)
                    ldsm4(b[nh], bt + (swB[nh] ^ kx));
#pragma unroll
                for (int mi = 0; mi < 4; mi++) {
                    mma16816(accL[mi][0], a[mi], b[0][0], b[0][1]);
                    mma16816(accL[mi][1], a[mi], b[0][2], b[0][3]);
                    mma16816(accL[mi][2], a[mi], b[1][0], b[1][1]);
                    mma16816(accL[mi][3], a[mi], b[1][2], b[1][3]);
                }
            }
        }
        __syncthreads();
    }

    // ---- epilogue ----
    if (z < 2) {
        uint16_t* p0 = z ? g_kp[0] : g_qp[0];
        uint16_t* p1 = z ? g_kp[1] : g_qp[1];
        uint16_t* p2 = z ? g_kp[2] : g_qp[2];
#pragma unroll
        for (int mi = 0; mi < 4; mi++) {
            const int r0 = bm + wm * 64 + mi * 16 + (l >> 2);
#pragma unroll
            for (int ni = 0; ni < 4; ni++) {
                const int cb = bn + wn * 32 + ni * 8 + 2 * (l & 3);
                const float bx = bias[cb], by = bias[cb + 1];
                const float o00 = accH[mi][ni][0] + accL[mi][ni][0] + bx;
                const float o01 = accH[mi][ni][1] + accL[mi][ni][1] + by;
                const float o10 = accH[mi][ni][2] + accL[mi][ni][2] + bx;
                const float o11 = accH[mi][ni][3] + accL[mi][ni][3] + by;
                uint16_t a0, a1, a2, b0, b1, b2;
                split3(o00, a0, a1, a2);
                split3(o01, b0, b1, b2);
                const size_t i0 = (size_t)r0 * EE + cb;
                *(ushort2*)&p0[i0] = make_ushort2(a0, b0);
                *(ushort2*)&p1[i0] = make_ushort2(a1, b1);
                *(ushort2*)&p2[i0] = make_ushort2(a2, b2);
                split3(o10, a0, a1, a2);
                split3(o11, b0, b1, b2);
                const size_t i1 = (size_t)(r0 + 8) * EE + cb;
                *(ushort2*)&p0[i1] = make_ushort2(a0, b0);
                *(ushort2*)&p1[i1] = make_ushort2(a1, b1);
                *(ushort2*)&p2[i1] = make_ushort2(a2, b2);
            }
        }
    } else {
#pragma unroll
        for (int mi = 0; mi < 4; mi++) {
            const int r0 = bm + wm * 64 + mi * 16 + (l >> 2);
#pragma unroll
            for (int ni = 0; ni < 4; ni++) {
                const int cb = bn + wn * 32 + ni * 8 + 2 * (l & 3);
                const float bx = bias[cb], by = bias[cb + 1];
                float2 v0 = make_float2(accH[mi][ni][0] + accL[mi][ni][0] + bx,
                                        accH[mi][ni][1] + accL[mi][ni][1] + by);
                float2 v1 = make_float2(accH[mi][ni][2] + accL[mi][ni][2] + bx,
                                        accH[mi][ni][3] + accL[mi][ni][3] + by);
                *(float2*)(Cv + (size_t)r0 * EE + cb) = v0;
                *(float2*)(Cv + (size_t)(r0 + 8) * EE + cb) = v1;
            }
        }
    }
}

// ===========================================================================
// Hybrid flash attention (R16 structure): QK^T on HMMA, PV on f32x2.
// R17 change: correction chains split into aL ((1,0),(0,1)) + aM
// ((2,0),(1,1),(0,2)) for ~3x tensor-chain ILP (RAW-stall fix).
// No-max softmax. Smem: QP 3x16K | KP 3x16K | V 2x32K | Pt 128x132x4.
// ===========================================================================
#define A_QP_OFF 0
#define A_KP_OFF 49152
#define A_V_OFF  98304
#define A_PT_OFF 163840
#define ATTN_SMEM (163840 + 128 * 132 * 4)   // 231424

__global__ __launch_bounds__(256, 1)
void attn_h(float* __restrict__ Out)
{
    extern __shared__ float sm[];
    const uint32_t sb = smem_u32(sm);
    const int tid = threadIdx.x;
    const int l   = tid & 31;
    const int wq  = tid >> 5;          // QK warp: q-rows wq*16..+15
    const int g   = tid & 15;          // PV lane group
    const int w   = tid >> 4;          // PV: q-rows w*8..+7

    const int b  = blockIdx.z;
    const int h  = blockIdx.y;
    const int q0 = blockIdx.x * 128;
    const int hofs = h * 64;
    const size_t rowbase = (size_t)b * SS;
    const size_t base = (size_t)b * SS * EE + (size_t)h * DD;

    const uint32_t swA = sw128((uint32_t)(((wq << 4) + (l & 15)) * 128
                                          + ((l >> 4) << 4)));

    // ---- prologue loads: Q planes + tile 0 (K planes + V) ----
#pragma unroll
    for (int i = 0; i < 12; i++) {
        const int idx = tid + i * 256;
        const int plane = idx >> 10;
        const int rem = idx & 1023;
        const int r = rem >> 3, c8 = rem & 7;
        const uint16_t* src = &g_qp[plane][(rowbase + q0 + r) * EE + hofs + c8 * 8];
        CPASYNC16(sb + A_QP_OFF + plane * 16384 + sw128((uint32_t)(r * 128 + c8 * 16)), src);
    }
    auto prefetch_kv = [&](int kt, int st) {
#pragma unroll
        for (int i = 0; i < 12; i++) {
            const int idx = tid + i * 256;
            const int plane = idx >> 10;
            const int rem = idx & 1023;
            const int r = rem >> 3, c8 = rem & 7;
            const uint16_t* src = &g_kp[plane][(rowbase + kt * 128 + r) * EE + hofs + c8 * 8];
            CPASYNC16(sb + A_KP_OFF + plane * 16384 + sw128((uint32_t)(r * 128 + c8 * 16)), src);
        }
#pragma unroll
        for (int i = 0; i < 8; i++) {
            const int idx = tid + i * 256;
            const int r = idx >> 4, c = idx & 15;
            const float* src = g_v + base + (size_t)(kt * 128 + r) * EE + c * 4;
            CPASYNC16(sb + A_V_OFF + st * 32768 + (uint32_t)(r * 256 + c * 16), src);
        }
        CP_COMMIT();
    };
    prefetch_kv(0, 0);

    float Sf[64];
    float lrs0 = 0.0f, lrs1 = 0.0f;
    u64 o2[4][4];
#pragma unroll
    for (int j2 = 0; j2 < 4; j2++)
#pragma unroll
        for (int dd = 0; dd < 4; dd++) o2[j2][dd] = 0ULL;

    // ---- S for one 16-key group: split correction accumulators (aL, aM) ----
    auto S_grp = [&](int grp) {
        const uint32_t swB = sw128((uint32_t)((grp * 16 + (l >> 4) * 8 + (l & 7)) * 128
                                              + (((l >> 3) & 1) << 4)));
        float aH[8], aL[8], aM[8];
#pragma unroll
        for (int c = 0; c < 8; c++) { aH[c] = 0.0f; aL[c] = 0.0f; aM[c] = 0.0f; }
#pragma unroll
        for (int ks = 0; ks < 4; ks++) {
            const uint32_t kx = (uint32_t)(ks << 5);
            uint32_t aq[3][4], bk[3][4];
#pragma unroll
            for (int p = 0; p < 3; p++)
                ldsm4(aq[p], sb + A_QP_OFF + p * 16384 + (swA ^ kx));
#pragma unroll
            for (int p = 0; p < 3; p++)
                ldsm4(bk[p], sb + A_KP_OFF + p * 16384 + (swB ^ kx));
            {
                float t[4];
                mma16816_z(t, aq[0], bk[0][0], bk[0][1]);
                aH[0] += t[0]; aH[1] += t[1]; aH[2] += t[2]; aH[3] += t[3];
                mma16816_z(t, aq[0], bk[0][2], bk[0][3]);
                aH[4] += t[0]; aH[5] += t[1]; aH[6] += t[2]; aH[7] += t[3];
            }
            // aL: (1,0), (0,1)   aM: (2,0), (1,1), (0,2)  — independent chains
            mma16816(aL,     aq[1], bk[0][0], bk[0][1]);
            mma16816(aL + 4, aq[1], bk[0][2], bk[0][3]);
            mma16816(aM,     aq[2], bk[0][0], bk[0][1]);
            mma16816(aM + 4, aq[2], bk[0][2], bk[0][3]);
            mma16816(aL,     aq[0], bk[1][0], bk[1][1]);
            mma16816(aL + 4, aq[0], bk[1][2], bk[1][3]);
            mma16816(aM,     aq[1], bk[1][0], bk[1][1]);
            mma16816(aM + 4, aq[1], bk[1][2], bk[1][3]);
            mma16816(aM,     aq[0], bk[2][0], bk[2][1]);
            mma16816(aM + 4, aq[0], bk[2][2], bk[2][3]);
        }
#pragma unroll
        for (int c = 0; c < 8; c++)
            Sf[grp * 8 + c] = __expf(floorf((aH[c] + (aL[c] + aM[c])) * 0.125f));
        lrs0 += Sf[grp*8+0] + Sf[grp*8+1] + Sf[grp*8+4] + Sf[grp*8+5];
        lrs1 += Sf[grp*8+2] + Sf[grp*8+3] + Sf[grp*8+6] + Sf[grp*8+7];
    };

    auto PV_chunk = [&](int grp, const float* Vs) {
        const ulonglong2* Pt16 = (const ulonglong2*)(sm + A_PT_OFF / 4);
#pragma unroll
        for (int kk = 0; kk < 16; kk++) {
            const int k = grp * 16 + kk;
            const ulonglong2 pA = Pt16[k * 33 + 2 * w];
            const ulonglong2 pB = Pt16[k * 33 + 2 * w + 1];
            const float4 vv = *(const float4*)&Vs[(k << 6) + (g << 2)];
            const u64 pp[4] = {pA.x, pA.y, pB.x, pB.y};
            const u64 vd[4] = {dup2(vv.x), dup2(vv.y), dup2(vv.z), dup2(vv.w)};
#pragma unroll
            for (int j2 = 0; j2 < 4; j2++)
#pragma unroll
                for (int dd = 0; dd < 4; dd++)
                    fma2(o2[j2][dd], pp[j2], vd[dd]);
        }
    };

    auto Ptstore = [&]() {
        float* PtF = sm + A_PT_OFF / 4;
        const int r0 = wq * 16 + (l >> 2);
#pragma unroll
        for (int grp = 0; grp < 8; grp++)
#pragma unroll
            for (int s = 0; s < 2; s++) {
                const int c = grp * 16 + s * 8 + 2 * (l & 3);
                PtF[c * 132 + r0]           = Sf[grp*8 + s*4 + 0];
                PtF[(c + 1) * 132 + r0]     = Sf[grp*8 + s*4 + 1];
                PtF[c * 132 + r0 + 8]       = Sf[grp*8 + s*4 + 2];
                PtF[(c + 1) * 132 + r0 + 8] = Sf[grp*8 + s*4 + 3];
            }
    };

    // ---- pipeline ----
    CP_WAIT0();
    __syncthreads();
#pragma unroll 1
    for (int grp = 0; grp < 8; grp++) S_grp(grp);
    __syncthreads();
    Ptstore();
    prefetch_kv(1, 1);

#pragma unroll 1
    for (int i = 0; i < 15; i++) {
        CP_WAIT0();
        __syncthreads();
        const float* Vs = sm + A_V_OFF / 4 + (i & 1) * 8192;
#pragma unroll 1
        for (int grp = 0; grp < 8; grp++) {
            S_grp(grp);
            PV_chunk(grp, Vs);
        }
        __syncthreads();
        Ptstore();
        if (i + 2 <= 15) prefetch_kv(i + 2, (i + 2) & 1);
    }
    __syncthreads();
    {
        const float* Vs = sm + A_V_OFF / 4 + (15 & 1) * 8192;
#pragma unroll 1
        for (int grp = 0; grp < 8; grp++) PV_chunk(grp, Vs);
    }

    // ---- epilogue ----
    lrs0 += __shfl_xor_sync(0xffffffffu, lrs0, 1);
    lrs0 += __shfl_xor_sync(0xffffffffu, lrs0, 2);
    lrs1 += __shfl_xor_sync(0xffffffffu, lrs1, 1);
    lrs1 += __shfl_xor_sync(0xffffffffu, lrs1, 2);
    __syncthreads();
    float* lrs_sm = sm;
    if ((l & 3) == 0) {
        lrs_sm[wq * 16 + (l >> 2)]     = lrs0;
        lrs_sm[wq * 16 + (l >> 2) + 8] = lrs1;
    }
    __syncthreads();

#pragma unroll
    for (int j = 0; j < 8; j++) {
        const int j2 = j >> 1;
        const int r = w * 8 + j;
        const float inv = 1.0f / lrs_sm[r];
        float o[4];
#pragma unroll
        for (int dd = 0; dd < 4; dd++) {
            float lo, hi;
            unpack2(lo, hi, o2[j2][dd]);
            o[dd] = (j & 1) ? hi : lo;
        }
        *(float4*)(Out + base + (size_t)(q0 + r) * EE + (g << 2)) =
            make_float4(o[0] * inv, o[1] * inv, o[2] * inv, o[3] * inv);
    }
}

// ---------------------------------------------------------------------------
extern "C" void kernel_launch(void* const* d_in, const int* in_sizes, int n_in,
                              void* d_out, int out_size)
{
    const float* key   = (const float*)d_in[0];
    const float* query = (const float*)d_in[1];
    const float* value = (const float*)d_in[2];
    const float* Wq    = (const float*)d_in[3];
    const float* bq    = (const float*)d_in[4];
    const float* Wk    = (const float*)d_in[5];
    const float* bk    = (const float*)d_in[6];
    const float* Wv    = (const float*)d_in[7];
    const float* bv    = (const float*)d_in[8];
    float* out = (float*)d_out;

    void* pv = 0;
    cudaGetSymbolAddress(&pv, g_v);

    cudaFuncSetAttribute(proj_mma, cudaFuncAttributeMaxDynamicSharedMemorySize,
                         PROJ_SMEM);
    cudaFuncSetAttribute(attn_h, cudaFuncAttributeMaxDynamicSharedMemorySize,
                         ATTN_SMEM);

    dim3 sgrid(MM * EE / 1024, 3);
    split_act<<<sgrid, 256>>>(query, key, value);
    dim3 wgrid(EE * EE / 1024, 3);
    split_w<<<wgrid, 256>>>(Wq, Wk, Wv);

    dim3 pgrid(EE / 128, MM / 128, 3);
    proj_mma<<<pgrid, 256, PROJ_SMEM>>>(bq, bk, bv, (float*)pv);

    dim3 agrid(SS / 128, HH, BB);
    attn_h<<<agrid, 256, ATTN_SMEM>>>(out);
}